// round 11
// baseline (speedup 1.0000x reference)
#include <cuda_runtime.h>
#include <cuda_bf16.h>
#include <cstdint>

#define FULL 0xffffffffu

// Order-preserving float->uint map (2 SASS ops)
__device__ __forceinline__ unsigned f2o(float f) {
    unsigned b = __float_as_uint(f);
    return b ^ ((unsigned)((int)b >> 31) | 0x80000000u);
}
// inverse map (bijective)
__device__ __forceinline__ float o2f(unsigned x) {
    unsigned b = x ^ ((unsigned)((int)(~x) >> 31) | 0x80000000u);
    return __uint_as_float(b);
}
// 1-MUFU reciprocal
__device__ __forceinline__ float frcp(float x) {
    float r;
    asm("rcp.approx.ftz.f32 %0, %1;" : "=f"(r) : "f"(x));
    return r;
}

// FP64-pipe compare-exchange: ascending double == descending (key, inv-id)
// (all packed patterns are negative doubles -> IEEE order inverts u64 order)
#define CSWAP(A, B)                                     \
    {                                                   \
        double mn = fmin(s[A], s[B]);                   \
        double mx = fmax(s[A], s[B]);                   \
        s[A] = mn;                                      \
        s[B] = mx;                                      \
    }

// Two tokens per warp: half = lane>>4, q = lane&15.
// Lane q owns experts [q*16, q*16+16). Group (32 experts) = lane pair (2g, 2g+1).
__global__ void __launch_bounds__(256, 8)
noaux_router_kernel(const float* __restrict__ logits,
                    const float* __restrict__ bias,
                    float* __restrict__ out,
                    int T, int write_ids)
{
    __shared__ float sbias[16 * 20];          // padded: row r at [r*20 .. r*20+15]
    __shared__ double pk[8 * 256];            // tail (slots 1..7) + pad, [slot*256+tid]
    {
        const int t = threadIdx.x;
        sbias[(t >> 4) * 20 + (t & 15)] = bias[t];
    }
    __syncthreads();

    const int warpid = blockIdx.x * (blockDim.x >> 5) + (threadIdx.x >> 5);
    if (warpid * 2 >= T) return;
    const int lane = threadIdx.x & 31;
    const int half = lane >> 4;
    const int q    = lane & 15;
    const int tok  = warpid * 2 + half;
    const unsigned hm = 0xFFFFu << (half << 4);   // this token's 16-lane mask

    // ---- load 16 logits (4x LDG.128, batched for MLP) ----
    const float4* lp = reinterpret_cast<const float4*>(logits + (size_t)tok * 256 + q * 16);
    float4 xv4[4];
    #pragma unroll
    for (int i = 0; i < 4; i++) xv4[i] = lp[i];

    // ---- corrected scores (fast sigmoid: EX2 + RCP.approx) + in-lane top-2 ----
    // (identical math to rounds 9/10 -> selection outcomes bit-identical)
    float mk[16];
    float m1 = -INFINITY, m2 = -INFINITY;
    #pragma unroll
    for (int c = 0; c < 4; c++) {
        const float4 bv = *reinterpret_cast<const float4*>(&sbias[q * 20 + c * 4]);
        const float* xp = reinterpret_cast<const float*>(&xv4[c]);
        const float* bp = reinterpret_cast<const float*>(&bv);
        #pragma unroll
        for (int i = 0; i < 4; i++) {
            float e = __expf(-xp[i]);
            float v = frcp(1.0f + e) + bp[i];
            mk[c * 4 + i] = v;
            m2 = fmaxf(m2, fminf(m1, v));
            m1 = fmaxf(m1, v);
        }
    }
    // merge with group partner (lane^1 stays inside the half)
    {
        float o1 = __shfl_xor_sync(FULL, m1, 1);
        float o2 = __shfl_xor_sync(FULL, m2, 1);
        float nm2 = fmaxf(fminf(m1, o1), fmaxf(m2, o2));
        m1 = fmaxf(m1, o1);
        m2 = nm2;
    }
    const float gscore = m1 + m2;                 // uniform across the pair
    const int   myg    = q >> 1;

    // ---- top-4 of 8 groups (tie-break: lowest group index) ----
    int cnt = 0;
    #pragma unroll
    for (int g = 0; g < 8; g++) {
        float gsg = __shfl_sync(FULL, gscore, (half << 4) + 2 * g);
        cnt += (gsg > gscore) || (gsg == gscore && g < myg);
    }
    const bool sel = (cnt < 4);

    // ---- redistribution: 8 live lanes x 16 -> 16 lanes x 8 ----
    const unsigned ball = __ballot_sync(FULL, sel);
    const unsigned hb   = (ball >> (half << 4)) & 0xFFFFu;    // live lanes in half
    const unsigned dmask = ~hb & 0xFFFFu;

    int n = __popc(dmask & ((1u << q) - 1u));     // my rank among dead lanes
    unsigned mm = hb; int off = 0, c;             // n-th set bit of hb
    c = __popc(mm & 0xFFu); if (n >= c) { n -= c; off = 8;  mm >>= 8; }
    c = __popc(mm & 0xFu);  if (n >= c) { n -= c; off += 4; mm >>= 4; }
    c = __popc(mm & 0x3u);  if (n >= c) { n -= c; off += 2; mm >>= 2; }
    c = (int)(mm & 1u);     if (n >= c) { off += 1; }
    const int src_q = off;
    const int srclane = (half << 4) + (sel ? q : src_q);

    // publish + pack into 64-bit patterns: hi = key32, lo = (511 - id) << 23
    double s[8];
    const int ibase = (sel ? (q << 4) : ((src_q << 4) + 8));
    #pragma unroll
    for (int j = 0; j < 8; j++) {
        float up = __shfl_sync(FULL, mk[8 + j], srclane);
        float v  = sel ? mk[j] : up;
        unsigned key = f2o(v);
        unsigned lo  = (unsigned)(511 - (ibase + j)) << 23;
        s[j] = __hiloint2double((int)key, (int)lo);
    }

    // ---- sort 8 ascending as doubles (= descending by (key, inv-id)) ----
    // 19-comparator optimal network, each comparator = DMNMX pair (FP64 pipe)
    CSWAP(0,1) CSWAP(2,3) CSWAP(4,5) CSWAP(6,7)
    CSWAP(0,2) CSWAP(1,3) CSWAP(4,6) CSWAP(5,7)
    CSWAP(1,2) CSWAP(5,6) CSWAP(0,4) CSWAP(3,7)
    CSWAP(1,5) CSWAP(2,6)
    CSWAP(1,4) CSWAP(3,6)
    CSWAP(2,4) CSWAP(3,5)
    CSWAP(3,4)

    // tail -> conflict-free interleaved smem (slots 1..7); pad slot (deterministic)
    #pragma unroll
    for (int j = 1; j < 8; j++)
        pk[(j - 1) * 256 + threadIdx.x] = s[j];
    pk[7 * 256 + threadIdx.x] = 0.0;

    unsigned khi = (unsigned)__double2hiint(s[0]);   // head key
    unsigned klo = (unsigned)__double2loint(s[0]);   // head inv-id field

    // ---- global top-8 per half: 8 rounds, both tokens in lockstep ----
    unsigned mkey = 0, midf = 0;
    const double* pkp = pk + threadIdx.x;
    #pragma unroll
    for (int r = 0; r < 8; r++) {
        double nd = *pkp;                              // prefetch next (conflict-free)
        unsigned m   = __reduce_max_sync(hm, khi);
        unsigned cnd = (khi == m) ? klo : 0u;          // klo never 0 for real cands
        unsigned ml  = __reduce_max_sync(hm, cnd);     // highest inv-id = lowest id
        bool win     = (cnd == ml);
        bool cap     = (q == r);
        mkey = cap ? m  : mkey;
        midf = cap ? ml : midf;
        khi = win ? (unsigned)__double2hiint(nd) : khi;
        klo = win ? (unsigned)__double2loint(nd) : klo;
        pkp = win ? pkp + 256 : pkp;
    }
    const int myid = 511 - (int)(midf >> 23);

    // ---- epilogue: recover uncorrected sigmoid from winner key ----
    float sc = o2f(mkey);
    float b  = sbias[((myid >> 4) * 20) + (myid & 15)];
    float w  = sc - b;                             // (sig+bias)-bias ~= sig

    float wsum = w;                                // xor d<8 stays within octet
    #pragma unroll
    for (int d = 1; d < 8; d <<= 1)
        wsum += __shfl_xor_sync(FULL, wsum, d);

    if (q < 8) {
        const float scale = 2.5f * frcp(wsum + 1e-20f);
        out[(size_t)tok * 8 + q] = w * scale;
        if (write_ids)
            out[(size_t)T * 8 + (size_t)tok * 8 + q] = (float)myid;
    }
}

extern "C" void kernel_launch(void* const* d_in, const int* in_sizes, int n_in,
                              void* d_out, int out_size)
{
    const float* logits = (const float*)d_in[0];
    const float* bias   = (const float*)d_in[1];
    const int E = in_sizes[1];            // 256
    const int T = in_sizes[0] / E;        // 131072
    float* out = (float*)d_out;

    const int write_ids = (out_size >= T * 16) ? 1 : 0;

    const int warps = (T + 1) / 2;        // 2 tokens per warp
    const int warps_per_block = 8;        // 256 threads
    const int blocks = (warps + warps_per_block - 1) / warps_per_block;
    noaux_router_kernel<<<blocks, 256>>>(logits, bias, out, T, write_ids);
}

// round 12
// speedup vs baseline: 2.7638x; 2.7638x over previous
#include <cuda_runtime.h>
#include <cuda_bf16.h>
#include <cstdint>

#define FULL 0xffffffffu

// Order-preserving float->uint map (2 SASS ops)
__device__ __forceinline__ unsigned f2o(float f) {
    unsigned b = __float_as_uint(f);
    return b ^ ((unsigned)((int)b >> 31) | 0x80000000u);
}
// inverse map (bijective)
__device__ __forceinline__ float o2f(unsigned x) {
    unsigned b = x ^ ((unsigned)((int)(~x) >> 31) | 0x80000000u);
    return __uint_as_float(b);
}
// 1-MUFU reciprocal
__device__ __forceinline__ float frcp(float x) {
    float r;
    asm("rcp.approx.ftz.f32 %0, %1;" : "=f"(r) : "f"(x));
    return r;
}

// descending compare-exchange on float (score,id)
#define CSWAP(A, B)                                     \
    {                                                   \
        bool p = s[A] < s[B];                           \
        float ts = p ? s[B] : s[A];                     \
        s[B] = p ? s[A] : s[B];                         \
        s[A] = ts;                                      \
        int ti = p ? id[B] : id[A];                     \
        id[B] = p ? id[A] : id[B];                      \
        id[A] = ti;                                     \
    }

// Two tokens per warp: half = lane>>4, q = lane&15.
// Lane q owns experts [q*16, q*16+16). Group (32 experts) = lane pair (2g, 2g+1).
__global__ void __launch_bounds__(256, 8)
noaux_router_kernel(const float* __restrict__ logits,
                    const float* __restrict__ bias,
                    float* __restrict__ out,
                    int T, int write_ids)
{
    __shared__ float sbias[16 * 20];          // padded: row r at [r*20 .. r*20+15]
    __shared__ unsigned pk[8 * 256];          // tail keys, interleaved [slot*256+tid]
    {                                         // slot 7 = pad (never a real candidate)
        const int t = threadIdx.x;
        sbias[(t >> 4) * 20 + (t & 15)] = bias[t];
    }
    __syncthreads();

    const int warpid = blockIdx.x * (blockDim.x >> 5) + (threadIdx.x >> 5);
    if (warpid * 2 >= T) return;
    const int lane = threadIdx.x & 31;
    const int half = lane >> 4;
    const int q    = lane & 15;
    const int tok  = warpid * 2 + half;
    const unsigned hm = 0xFFFFu << (half << 4);   // this token's 16-lane mask

    // ---- load 16 logits (4x LDG.128, batched for MLP) ----
    const float4* lp = reinterpret_cast<const float4*>(logits + (size_t)tok * 256 + q * 16);
    float4 xv4[4];
    #pragma unroll
    for (int i = 0; i < 4; i++) xv4[i] = lp[i];

    // ---- corrected scores (fast sigmoid: EX2 + RCP.approx) ----
    // (identical math to rounds 9/10 -> selection outcomes bit-identical)
    float mk[16];
    #pragma unroll
    for (int c = 0; c < 4; c++) {
        const float4 bv = *reinterpret_cast<const float4*>(&sbias[q * 20 + c * 4]);
        const float* xp = reinterpret_cast<const float*>(&xv4[c]);
        const float* bp = reinterpret_cast<const float*>(&bv);
        #pragma unroll
        for (int i = 0; i < 4; i++) {
            float e = __expf(-xp[i]);
            mk[c * 4 + i] = frcp(1.0f + e) + bp[i];
        }
    }

    // ---- in-lane top-2 of 16: select-free tournament (exact values) ----
    // merge identity: second(A,B) = max(min(h1,h2), max(l1,l2))  (l_loser <= h_loser)
    float h[8], l[8];
    #pragma unroll
    for (int i = 0; i < 8; i++) {
        h[i] = fmaxf(mk[2 * i], mk[2 * i + 1]);
        l[i] = fminf(mk[2 * i], mk[2 * i + 1]);
    }
    #pragma unroll
    for (int st = 4; st >= 1; st >>= 1) {
        #pragma unroll
        for (int i = 0; i < st; i++) {
            float H  = fmaxf(h[i], h[i + st]);
            float L  = fmaxf(fminf(h[i], h[i + st]), fmaxf(l[i], l[i + st]));
            h[i] = H; l[i] = L;
        }
    }
    float m1 = h[0], m2 = l[0];
    // merge with group partner (lane^1 stays inside the half)
    {
        float o1 = __shfl_xor_sync(FULL, m1, 1);
        float o2 = __shfl_xor_sync(FULL, m2, 1);
        float nm2 = fmaxf(fminf(m1, o1), fmaxf(m2, o2));
        m1 = fmaxf(m1, o1);
        m2 = nm2;
    }
    const float gscore = m1 + m2;                 // uniform across the pair
    const int   myg    = q >> 1;

    // ---- top-4 of 8 groups (tie-break: lowest group index) ----
    int cnt = 0;
    #pragma unroll
    for (int g = 0; g < 8; g++) {
        float gsg = __shfl_sync(FULL, gscore, (half << 4) + 2 * g);
        cnt += (gsg > gscore) || (gsg == gscore && g < myg);
    }
    const bool sel = (cnt < 4);

    // ---- redistribution: 8 live lanes x 16 -> 16 lanes x 8 ----
    const unsigned ball = __ballot_sync(FULL, sel);
    const unsigned hb   = (ball >> (half << 4)) & 0xFFFFu;    // live lanes in half
    const unsigned dmask = ~hb & 0xFFFFu;

    int n = __popc(dmask & ((1u << q) - 1u));     // my rank among dead lanes
    unsigned mm = hb; int off = 0, c;             // n-th set bit of hb
    c = __popc(mm & 0xFFu); if (n >= c) { n -= c; off = 8;  mm >>= 8; }
    c = __popc(mm & 0xFu);  if (n >= c) { n -= c; off += 4; mm >>= 4; }
    c = __popc(mm & 0x3u);  if (n >= c) { n -= c; off += 2; mm >>= 2; }
    c = (int)(mm & 1u);     if (n >= c) { off += 1; }
    const int src_q = off;
    const int srclane = (half << 4) + (sel ? q : src_q);

    float s[8];
    int id[8];
    const int ibase = (sel ? (q << 4) : ((src_q << 4) + 8));
    #pragma unroll
    for (int j = 0; j < 8; j++) {
        float up = __shfl_sync(FULL, mk[8 + j], srclane);
        s[j]  = sel ? mk[j] : up;
        id[j] = ibase + j;
    }

    // ---- sort 8 descending in float domain (19-comparator network, stable) ----
    CSWAP(0,1) CSWAP(2,3) CSWAP(4,5) CSWAP(6,7)
    CSWAP(0,2) CSWAP(1,3) CSWAP(4,6) CSWAP(5,7)
    CSWAP(1,2) CSWAP(5,6) CSWAP(0,4) CSWAP(3,7)
    CSWAP(1,5) CSWAP(2,6)
    CSWAP(1,4) CSWAP(3,6)
    CSWAP(2,4) CSWAP(3,5)
    CSWAP(3,4)

    // tail keys -> conflict-free interleaved smem (convert at store)
    #pragma unroll
    for (int j = 1; j < 8; j++)
        pk[(j - 1) * 256 + threadIdx.x] = f2o(s[j]);

    unsigned khead = f2o(s[0]);
    // full id queue as 8 packed bytes (head included)
    unsigned idlo  = (unsigned)id[0] | ((unsigned)id[1] << 8) |
                     ((unsigned)id[2] << 16) | ((unsigned)id[3] << 24);
    unsigned idhi  = (unsigned)id[4] | ((unsigned)id[5] << 8) |
                     ((unsigned)id[6] << 16) | ((unsigned)id[7] << 24);

    // ---- global top-8 per half: 8 rounds, both tokens in lockstep ----
    unsigned myid = 0, mkey = 0;
    const unsigned* pkp = pk + threadIdx.x;        // slot pointer (incremented on win)
    #pragma unroll
    for (int r = 0; r < 8; r++) {
        unsigned nk  = *pkp;                       // prefetch, conflict-free
        unsigned m   = __reduce_max_sync(hm, khead);
        unsigned cnd = (khead == m) ? (idlo & 0xFFu) : 0x1FFu;
        unsigned wid = __reduce_min_sync(hm, cnd); // lowest expert id on ties
        bool win     = (cnd == wid);
        bool cap     = (q == r);
        myid = cap ? wid : myid;
        mkey = cap ? m   : mkey;
        unsigned nlo = __funnelshift_r(idlo, idhi, 8);
        pkp   = win ? pkp + 256 : pkp;
        khead = win ? nk  : khead;
        idlo  = win ? nlo : idlo;
        idhi  = win ? (idhi >> 8) : idhi;
    }

    // ---- epilogue: recover uncorrected sigmoid from winner key ----
    float sc = o2f(mkey);
    float b  = sbias[(((int)myid >> 4) * 20) + ((int)myid & 15)];
    float w  = sc - b;                             // (sig+bias)-bias ~= sig

    float wsum = w;                                // xor d<8 stays within octet
    #pragma unroll
    for (int d = 1; d < 8; d <<= 1)
        wsum += __shfl_xor_sync(FULL, wsum, d);

    if (q < 8) {
        const float scale = 2.5f * frcp(wsum + 1e-20f);
        out[(size_t)tok * 8 + q] = w * scale;
        if (write_ids)
            out[(size_t)T * 8 + (size_t)tok * 8 + q] = (float)myid;
    }
}

extern "C" void kernel_launch(void* const* d_in, const int* in_sizes, int n_in,
                              void* d_out, int out_size)
{
    const float* logits = (const float*)d_in[0];
    const float* bias   = (const float*)d_in[1];
    const int E = in_sizes[1];            // 256
    const int T = in_sizes[0] / E;        // 131072
    float* out = (float*)d_out;

    const int write_ids = (out_size >= T * 16) ? 1 : 0;

    const int warps = (T + 1) / 2;        // 2 tokens per warp
    const int warps_per_block = 8;        // 256 threads
    const int blocks = (warps + warps_per_block - 1) / warps_per_block;
    noaux_router_kernel<<<blocks, 256>>>(logits, bias, out, T, write_ids);
}

// round 13
// speedup vs baseline: 2.7966x; 1.0118x over previous
#include <cuda_runtime.h>
#include <cuda_bf16.h>
#include <cstdint>

#define FULL 0xffffffffu

// Order-preserving float->uint map (2 SASS ops)
__device__ __forceinline__ unsigned f2o(float f) {
    unsigned b = __float_as_uint(f);
    return b ^ ((unsigned)((int)b >> 31) | 0x80000000u);
}
// inverse map (bijective)
__device__ __forceinline__ float o2f(unsigned x) {
    unsigned b = x ^ ((unsigned)((int)(~x) >> 31) | 0x80000000u);
    return __uint_as_float(b);
}
// 1-MUFU reciprocal (same instruction as rounds 9-12 -> bit-identical)
__device__ __forceinline__ float frcp(float x) {
    float r;
    asm("rcp.approx.ftz.f32 %0, %1;" : "=f"(r) : "f"(x));
    return r;
}
// exp2 approx (the exact MUFU __expf lowers to)
__device__ __forceinline__ float ex2a(float x) {
    float r;
    asm("ex2.approx.f32 %0, %1;" : "=f"(r) : "f"(x));
    return r;
}
// packed fp32x2 (sm_103a dual-pump; rn per half => bit-identical to scalar)
__device__ __forceinline__ unsigned long long mul2(unsigned long long a, unsigned long long b) {
    unsigned long long r;
    asm("mul.rn.f32x2 %0, %1, %2;" : "=l"(r) : "l"(a), "l"(b));
    return r;
}
__device__ __forceinline__ unsigned long long add2(unsigned long long a, unsigned long long b) {
    unsigned long long r;
    asm("add.rn.f32x2 %0, %1, %2;" : "=l"(r) : "l"(a), "l"(b));
    return r;
}
__device__ __forceinline__ float lo32(unsigned long long v) { return __uint_as_float((unsigned)v); }
__device__ __forceinline__ float hi32(unsigned long long v) { return __uint_as_float((unsigned)(v >> 32)); }
__device__ __forceinline__ unsigned long long pk2(float a, float b) {
    unsigned long long r;
    asm("mov.b64 %0, {%1, %2};" : "=l"(r) : "f"(a), "f"(b));
    return r;
}

union V4 { float4 f; unsigned long long u[2]; };

// descending compare-exchange on float (score,id)
#define CSWAP(A, B)                                     \
    {                                                   \
        bool p = s[A] < s[B];                           \
        float ts = p ? s[B] : s[A];                     \
        s[B] = p ? s[A] : s[B];                         \
        s[A] = ts;                                      \
        int ti = p ? id[B] : id[A];                     \
        id[B] = p ? id[A] : id[B];                      \
        id[A] = ti;                                     \
    }

// Two tokens per warp: half = lane>>4, q = lane&15.
// Lane q owns experts [q*16, q*16+16). Group (32 experts) = lane pair (2g, 2g+1).
__global__ void __launch_bounds__(256, 8)
noaux_router_kernel(const float* __restrict__ logits,
                    const float* __restrict__ bias,
                    float* __restrict__ out,
                    int T, int write_ids)
{
    __shared__ float sbias[16 * 20];          // padded: row r at [r*20 .. r*20+15]
    __shared__ unsigned pk[8 * 256];          // tail keys, interleaved [slot*256+tid]
    {
        const int t = threadIdx.x;
        sbias[(t >> 4) * 20 + (t & 15)] = bias[t];
    }
    __syncthreads();

    const int warpid = blockIdx.x * (blockDim.x >> 5) + (threadIdx.x >> 5);
    if (warpid * 2 >= T) return;
    const int lane = threadIdx.x & 31;
    const int half = lane >> 4;
    const int q    = lane & 15;
    const int tok  = warpid * 2 + half;
    const unsigned hm = 0xFFFFu << (half << 4);   // this token's 16-lane mask

    // ---- load 16 logits (4x LDG.128, batched for MLP) ----
    const float4* lp = reinterpret_cast<const float4*>(logits + (size_t)tok * 256 + q * 16);
    float4 xv4[4];
    #pragma unroll
    for (int i = 0; i < 4; i++) xv4[i] = lp[i];

    // ---- corrected scores via packed f32x2 glue around the 2 MUFUs ----
    // bit-identical to scalar path: (-x)*log2e == x*(-log2e); rn per half
    const unsigned long long NL2E = 0xBFB8AA3BBFB8AA3BULL;  // (-log2e, -log2e)
    const unsigned long long ONE2 = 0x3F8000003F800000ULL;  // (1.0f, 1.0f)
    float mk[16];
    #pragma unroll
    for (int c = 0; c < 4; c++) {
        V4 xv; xv.f = xv4[c];
        V4 bv; bv.f = *reinterpret_cast<const float4*>(&sbias[q * 20 + c * 4]);
        #pragma unroll
        for (int p = 0; p < 2; p++) {
            unsigned long long t = mul2(xv.u[p], NL2E);        // x * -log2e (pair)
            float e0 = ex2a(lo32(t));                          // MUFU.EX2
            float e1 = ex2a(hi32(t));
            unsigned long long u = add2(pk2(e0, e1), ONE2);    // 1 + e (pair)
            float r0 = frcp(lo32(u));                          // MUFU.RCP
            float r1 = frcp(hi32(u));
            unsigned long long sv = add2(pk2(r0, r1), bv.u[p]); // + bias (pair)
            mk[c * 4 + 2 * p]     = lo32(sv);
            mk[c * 4 + 2 * p + 1] = hi32(sv);
        }
    }

    // ---- in-lane top-2 of 16: select-free tournament (exact values) ----
    float h[8], l[8];
    #pragma unroll
    for (int i = 0; i < 8; i++) {
        h[i] = fmaxf(mk[2 * i], mk[2 * i + 1]);
        l[i] = fminf(mk[2 * i], mk[2 * i + 1]);
    }
    #pragma unroll
    for (int st = 4; st >= 1; st >>= 1) {
        #pragma unroll
        for (int i = 0; i < st; i++) {
            float H  = fmaxf(h[i], h[i + st]);
            float L  = fmaxf(fminf(h[i], h[i + st]), fmaxf(l[i], l[i + st]));
            h[i] = H; l[i] = L;
        }
    }
    float m1 = h[0], m2 = l[0];
    // merge with group partner (lane^1 stays inside the half)
    {
        float o1 = __shfl_xor_sync(FULL, m1, 1);
        float o2 = __shfl_xor_sync(FULL, m2, 1);
        float nm2 = fmaxf(fminf(m1, o1), fmaxf(m2, o2));
        m1 = fmaxf(m1, o1);
        m2 = nm2;
    }
    const float gscore = m1 + m2;                 // uniform across the pair
    const int   myg    = q >> 1;

    // ---- top-4 of 8 groups (tie-break: lowest group index) ----
    int cnt = 0;
    #pragma unroll
    for (int g = 0; g < 8; g++) {
        float gsg = __shfl_sync(FULL, gscore, (half << 4) + 2 * g);
        cnt += (gsg > gscore) || (gsg == gscore && g < myg);
    }
    const bool sel = (cnt < 4);

    // ---- redistribution: 8 live lanes x 16 -> 16 lanes x 8 ----
    const unsigned ball = __ballot_sync(FULL, sel);
    const unsigned hb   = (ball >> (half << 4)) & 0xFFFFu;    // live lanes in half
    const unsigned dmask = ~hb & 0xFFFFu;

    int n = __popc(dmask & ((1u << q) - 1u));     // my rank among dead lanes
    unsigned mm = hb; int off = 0, c;             // n-th set bit of hb
    c = __popc(mm & 0xFFu); if (n >= c) { n -= c; off = 8;  mm >>= 8; }
    c = __popc(mm & 0xFu);  if (n >= c) { n -= c; off += 4; mm >>= 4; }
    c = __popc(mm & 0x3u);  if (n >= c) { n -= c; off += 2; mm >>= 2; }
    c = (int)(mm & 1u);     if (n >= c) { off += 1; }
    const int src_q = off;
    const int srclane = (half << 4) + (sel ? q : src_q);

    float s[8];
    int id[8];
    const int ibase = (sel ? (q << 4) : ((src_q << 4) + 8));
    #pragma unroll
    for (int j = 0; j < 8; j++) {
        float up = __shfl_sync(FULL, mk[8 + j], srclane);
        s[j]  = sel ? mk[j] : up;
        id[j] = ibase + j;
    }

    // ---- sort 8 descending in float domain (19-comparator network, stable) ----
    CSWAP(0,1) CSWAP(2,3) CSWAP(4,5) CSWAP(6,7)
    CSWAP(0,2) CSWAP(1,3) CSWAP(4,6) CSWAP(5,7)
    CSWAP(1,2) CSWAP(5,6) CSWAP(0,4) CSWAP(3,7)
    CSWAP(1,5) CSWAP(2,6)
    CSWAP(1,4) CSWAP(3,6)
    CSWAP(2,4) CSWAP(3,5)
    CSWAP(3,4)

    // tail keys -> conflict-free interleaved smem (convert at store)
    #pragma unroll
    for (int j = 1; j < 8; j++)
        pk[(j - 1) * 256 + threadIdx.x] = f2o(s[j]);

    unsigned khead = f2o(s[0]);
    // full id queue as 8 packed bytes (head included)
    unsigned idlo  = (unsigned)id[0] | ((unsigned)id[1] << 8) |
                     ((unsigned)id[2] << 16) | ((unsigned)id[3] << 24);
    unsigned idhi  = (unsigned)id[4] | ((unsigned)id[5] << 8) |
                     ((unsigned)id[6] << 16) | ((unsigned)id[7] << 24);

    // ---- global top-8 per half: 8 rounds, both tokens in lockstep ----
    unsigned myid = 0, mkey = 0;
    const unsigned* pkp = pk + threadIdx.x;        // slot pointer (incremented on win)
    #pragma unroll
    for (int r = 0; r < 8; r++) {
        unsigned nk  = *pkp;                       // prefetch, conflict-free
        unsigned m   = __reduce_max_sync(hm, khead);
        unsigned cnd = (khead == m) ? (idlo & 0xFFu) : 0x1FFu;
        unsigned wid = __reduce_min_sync(hm, cnd); // lowest expert id on ties
        bool win     = (cnd == wid);
        bool cap     = (q == r);
        myid = cap ? wid : myid;
        mkey = cap ? m   : mkey;
        unsigned nlo = __funnelshift_r(idlo, idhi, 8);
        pkp   = win ? pkp + 256 : pkp;
        khead = win ? nk  : khead;
        idlo  = win ? nlo : idlo;
        idhi  = win ? (idhi >> 8) : idhi;
    }

    // ---- epilogue: recover uncorrected sigmoid from winner key ----
    float sc = o2f(mkey);
    float b  = sbias[(((int)myid >> 4) * 20) + ((int)myid & 15)];
    float w  = sc - b;                             // (sig+bias)-bias ~= sig

    float wsum = w;                                // xor d<8 stays within octet
    #pragma unroll
    for (int d = 1; d < 8; d <<= 1)
        wsum += __shfl_xor_sync(FULL, wsum, d);

    if (q < 8) {
        const float scale = 2.5f * frcp(wsum + 1e-20f);
        out[(size_t)tok * 8 + q] = w * scale;
        if (write_ids)
            out[(size_t)T * 8 + (size_t)tok * 8 + q] = (float)myid;
    }
}

extern "C" void kernel_launch(void* const* d_in, const int* in_sizes, int n_in,
                              void* d_out, int out_size)
{
    const float* logits = (const float*)d_in[0];
    const float* bias   = (const float*)d_in[1];
    const int E = in_sizes[1];            // 256
    const int T = in_sizes[0] / E;        // 131072
    float* out = (float*)d_out;

    const int write_ids = (out_size >= T * 16) ? 1 : 0;

    const int warps = (T + 1) / 2;        // 2 tokens per warp
    const int warps_per_block = 8;        // 256 threads
    const int blocks = (warps + warps_per_block - 1) / warps_per_block;
    noaux_router_kernel<<<blocks, 256>>>(logits, bias, out, T, write_ids);
}